// round 15
// baseline (speedup 1.0000x reference)
#include <cuda_runtime.h>

// multilayer_64948495450471 — analytic filters + f32x2 + view-split + 4px/thread.
// layers : [1, 3, 12, 384, 384] f32   (d_in[0])
// filters: analytic, not read
// out    : [1, 25, 3, 384, 384] f32
//
// Role 0: horizontal classes ll in {0,1,2}; role 1: ll in {3,4}.
// Each thread computes a 4-pixel strip (two packed f32x2 pairs A,B):
//   taps per row/layer = one LDG.128 + one scalar; outputs = STG.128.
// Layer-2 taps pre-scaled by c1*0.25 -> inner accumulate is 1 FFMA2/view/pair.

#define HH 384
#define WW 384
#define HW (HH * WW)

#define W_M2 (1.0f / 384.0f)
#define W_M1 (385.0f / 768.0f)
#define W_P1 (383.0f / 768.0f)
#define W_P2 (383.0f / 384.0f)

struct F2 { unsigned long long v; };

__device__ __forceinline__ F2 fpack(float lo, float hi) {
    F2 r; asm("mov.b64 %0, {%1, %2};" : "=l"(r.v) : "f"(lo), "f"(hi)); return r;
}
__device__ __forceinline__ F2 fbc(float w) { return fpack(w, w); }
__device__ __forceinline__ F2 ffma2(F2 a, F2 b, F2 c) {
    F2 r; asm("fma.rn.f32x2 %0, %1, %2, %3;" : "=l"(r.v) : "l"(a.v), "l"(b.v), "l"(c.v)); return r;
}
__device__ __forceinline__ F2 fmul2(F2 a, F2 b) {
    F2 r; asm("mul.rn.f32x2 %0, %1, %2;" : "=l"(r.v) : "l"(a.v), "l"(b.v)); return r;
}
__device__ __forceinline__ void funpack(F2 a, float& lo, float& hi) {
    asm("mov.b64 {%0, %1}, %2;" : "=f"(lo), "=f"(hi) : "l"(a.v));
}
__device__ __forceinline__ float4 ldg4(const float* p) {
    return __ldg(reinterpret_cast<const float4*>(p));
}

template <int ROLE>
__device__ __forceinline__ void worker(const float* __restrict__ layers,
                                       float* __restrict__ out,
                                       int x0, int y, int c)
{
    constexpr int NLL   = (ROLE == 0) ? 3 : 2;
    constexpr int LLOFF = (ROLE == 0) ? 0 : 3;

    const int xm = max(x0 - 1, 0);
    const int xp = min(x0 + 4, WW - 1);
    const int rows[3] = { max(y - 1, 0) * WW, y * WW, min(y + 1, HH - 1) * WW };

    const F2 NEG1 = fbc(-1.0f);
    const F2 WM2 = fbc(W_M2), WM1 = fbc(W_M1), WP1 = fbc(W_P1), WP2 = fbc(W_P2);
    const F2 QTR = fbc(0.25f);

    F2 accA[NLL * 5], accB[NLL * 5];
#pragma unroll
    for (int i = 0; i < NLL * 5; ++i) { accA[i] = fpack(0.f, 0.f); accB[i] = fpack(0.f, 0.f); }

#pragma unroll
    for (int r = 0; r < 4; ++r) {
        const int ch = r * 3 + c;
        const float* p0 = layers + (size_t)(0 * 12 + ch) * HW;   // layer c=-1
        const float* p1 = layers + (size_t)(1 * 12 + ch) * HW;   // identity layer
        const float* p2 = layers + (size_t)(2 * 12 + ch) * HW;   // layer c=+1

        // identity value, rank-mean 0.25 folded in; scales layer2 taps
        const float4 i4 = ldg4(p1 + rows[1] + x0);
        const F2 c1A = fmul2(fpack(i4.x, i4.y), QTR);
        const F2 c1B = fmul2(fpack(i4.z, i4.w), QTR);

        F2 H0A[NLL][3], H0B[NLL][3], H2A[NLL][3], H2B[NLL][3];
#pragma unroll
        for (int rr = 0; rr < 3; ++rr) {
            if (ROLE == 0) {
                // layer0 classes M2,M1,ident: taps {xm} + {x0..x3}
                const float  a_ = __ldg(p0 + rows[rr] + xm);
                const float4 q  = ldg4(p0 + rows[rr] + x0);
                {   // pair A (x0,x1)
                    const F2 t0 = fpack(a_, q.x), t1 = fpack(q.x, q.y);
                    const F2 d01 = ffma2(t0, NEG1, t1);
                    H0A[0][rr] = ffma2(WM2, d01, t0);
                    H0A[1][rr] = ffma2(WM1, d01, t0);
                    H0A[2][rr] = t1;
                }
                {   // pair B (x2,x3)
                    const F2 t0 = fpack(q.y, q.z), t1 = fpack(q.z, q.w);
                    const F2 d01 = ffma2(t0, NEG1, t1);
                    H0B[0][rr] = ffma2(WM2, d01, t0);
                    H0B[1][rr] = ffma2(WM1, d01, t0);
                    H0B[2][rr] = t1;
                }
                // layer2 classes 4,3,2 (scaled): taps {x0..x3} + {xp}
                const float4 rq = ldg4(p2 + rows[rr] + x0);
                const float  d_ = __ldg(p2 + rows[rr] + xp);
                {   // pair A
                    const F2 s1 = fmul2(fpack(rq.x, rq.y), c1A);
                    const F2 s2 = fmul2(fpack(rq.y, rq.z), c1A);
                    const F2 d12 = ffma2(s1, NEG1, s2);
                    H2A[0][rr] = ffma2(WP2, d12, s1);
                    H2A[1][rr] = ffma2(WP1, d12, s1);
                    H2A[2][rr] = s1;
                }
                {   // pair B
                    const F2 s1 = fmul2(fpack(rq.z, rq.w), c1B);
                    const F2 s2 = fmul2(fpack(rq.w, d_),  c1B);
                    const F2 d12 = ffma2(s1, NEG1, s2);
                    H2B[0][rr] = ffma2(WP2, d12, s1);
                    H2B[1][rr] = ffma2(WP1, d12, s1);
                    H2B[2][rr] = s1;
                }
            } else {
                // layer0 classes P1,P2: taps {x0..x3} + {xp}
                const float4 q  = ldg4(p0 + rows[rr] + x0);
                const float  d_ = __ldg(p0 + rows[rr] + xp);
                {   // pair A
                    const F2 t1 = fpack(q.x, q.y), t2 = fpack(q.y, q.z);
                    const F2 d12 = ffma2(t1, NEG1, t2);
                    H0A[0][rr] = ffma2(WP1, d12, t1);
                    H0A[1][rr] = ffma2(WP2, d12, t1);
                }
                {   // pair B
                    const F2 t1 = fpack(q.z, q.w), t2 = fpack(q.w, d_);
                    const F2 d12 = ffma2(t1, NEG1, t2);
                    H0B[0][rr] = ffma2(WP1, d12, t1);
                    H0B[1][rr] = ffma2(WP2, d12, t1);
                }
                // layer2 classes 1,0 (scaled): taps {xm} + {x0..x3}
                const float  a_ = __ldg(p2 + rows[rr] + xm);
                const float4 rq = ldg4(p2 + rows[rr] + x0);
                {   // pair A
                    const F2 s0 = fmul2(fpack(a_, rq.x), c1A);
                    const F2 s1 = fmul2(fpack(rq.x, rq.y), c1A);
                    const F2 d01 = ffma2(s0, NEG1, s1);
                    H2A[0][rr] = ffma2(WM1, d01, s0);
                    H2A[1][rr] = ffma2(WM2, d01, s0);
                }
                {   // pair B
                    const F2 s0 = fmul2(fpack(rq.y, rq.z), c1B);
                    const F2 s1 = fmul2(fpack(rq.z, rq.w), c1B);
                    const F2 d01 = ffma2(s0, NEG1, s1);
                    H2B[0][rr] = ffma2(WM1, d01, s0);
                    H2B[1][rr] = ffma2(WM2, d01, s0);
                }
            }
        }

#pragma unroll
        for (int i = 0; i < NLL; ++i) {
#pragma unroll
            for (int pr = 0; pr < 2; ++pr) {
                const F2 (*H0)[3] = pr ? H0B : H0A;
                const F2 (*H2)[3] = pr ? H2B : H2A;
                F2* acc = pr ? accB : accA;

                const F2 h0 = H0[i][0], h1 = H0[i][1], h2 = H0[i][2];
                const F2 a01 = ffma2(h0, NEG1, h1);
                const F2 a12 = ffma2(h1, NEG1, h2);
                F2 v[5];
                v[0] = ffma2(WM2, a01, h0);
                v[1] = ffma2(WM1, a01, h0);
                v[2] = h1;
                v[3] = ffma2(WP1, a12, h1);
                v[4] = ffma2(WP2, a12, h1);

                const F2 g0 = H2[i][0], g1 = H2[i][1], g2 = H2[i][2];
                const F2 b01 = ffma2(g0, NEG1, g1);
                const F2 b12 = ffma2(g1, NEG1, g2);
                F2 u[5];
                u[0] = ffma2(WM2, b01, g0);
                u[1] = ffma2(WM1, b01, g0);
                u[2] = g1;
                u[3] = ffma2(WP1, b12, g1);
                u[4] = ffma2(WP2, b12, g1);

#pragma unroll
                for (int kk = 0; kk < 5; ++kk)
                    acc[i * 5 + kk] = ffma2(v[kk], u[4 - kk], acc[i * 5 + kk]);
            }
        }
    }

    const size_t ob = ((size_t)c * HH + y) * WW + x0;
#pragma unroll
    for (int i = 0; i < NLL; ++i) {
#pragma unroll
        for (int kk = 0; kk < 5; ++kk) {
            const int a = kk * 5 + (LLOFF + i);
            float f0, f1, f2, f3;
            funpack(accA[i * 5 + kk], f0, f1);
            funpack(accB[i * 5 + kk], f2, f3);
            *reinterpret_cast<float4*>(out + (size_t)a * 3 * HW + ob)
                = make_float4(f0, f1, f2, f3);
        }
    }
}

__global__ __launch_bounds__(96, 4) void multilayer_kernel(
    const float* __restrict__ layers,
    float* __restrict__ out)
{
    const int x0 = 4 * threadIdx.x;     // 96 threads * 4 px = full 384-px row
    const int y  = blockIdx.y;
    const int z  = blockIdx.z;          // 0..5
    const int c  = (z < 3) ? z : z - 3;

    if (z < 3) worker<0>(layers, out, x0, y, c);
    else       worker<1>(layers, out, x0, y, c);
}

extern "C" void kernel_launch(void* const* d_in, const int* in_sizes, int n_in,
                              void* d_out, int out_size)
{
    const float* layers = (const float*)d_in[0];
    float* out = (float*)d_out;

    dim3 grid(1, HH, 6);    // (1, 384, 6) = 2304 blocks
    dim3 block(96);
    multilayer_kernel<<<grid, block>>>(layers, out);
}